// round 14
// baseline (speedup 1.0000x reference)
#include <cuda_runtime.h>
#include <cuda_fp16.h>
#include <cstdint>

#define TPB 256

// ---- fragment-linear fp16 weight buffer ----
// Per (layer, nt, kh, lane): uint4 = (b0 kt=2kh, b1 kt=2kh, b0 kt=2kh+1, b1 kt=2kh+1)
// where b0 = f16x2 (W[k=16kt+2cp][n], W[k=16kt+2cp+1][n]), b1 = k+8, n = nt*8+g.
#define OFF_S0 0        // K=32 (KH=1), N=64: 256
#define OFF_S1 256      // K=64 (KH=2), N=64: 512
#define OFF_S2 768      // K=64, N=16: 128
#define OFF_C0 896      // K=48 permuted (KH=2), N=64: 512
#define OFF_C1 1408     // 512
#define OFF_C2 1920     // 512
#define OFF_C3 2432     // K=64, N=8: 64
#define WU4    2496

__device__ uint4 wbuf[WU4];

__device__ __forceinline__ uint32_t h2pack(float a, float b) {
    __half2 h = __floats2half2_rn(a, b);
    return *(uint32_t*)&h;
}
__device__ __forceinline__ uint32_t h2relu(float a, float b) {
    __half2 h = __floats2half2_rn(a, b);
    h = __hmax2(h, __half2(__float2half_rn(0.f), __float2half_rn(0.f)));
    return *(uint32_t*)&h;
}

__device__ __forceinline__ void mma16(float* d, const uint32_t* a, uint32_t b0, uint32_t b1) {
    asm volatile(
        "mma.sync.aligned.m16n8k16.row.col.f32.f16.f16.f32 "
        "{%0,%1,%2,%3}, {%4,%5,%6,%7}, {%8,%9}, {%0,%1,%2,%3};"
        : "+f"(d[0]), "+f"(d[1]), "+f"(d[2]), "+f"(d[3])
        : "r"(a[0]), "r"(a[1]), "r"(a[2]), "r"(a[3]), "r"(b0), "r"(b1));
}

// First-touch variant: D = A*B + 0. Removes the per-layer accumulator
// zero-init MOVs (ptxas folds the zero C quad onto RZ / one shared reg).
__device__ __forceinline__ void mma16z(float* d, const uint32_t* a, uint32_t b0, uint32_t b1) {
    float z = 0.f;
    asm volatile(
        "mma.sync.aligned.m16n8k16.row.col.f32.f16.f16.f32 "
        "{%0,%1,%2,%3}, {%4,%5,%6,%7}, {%8,%9}, {%10,%10,%10,%10};"
        : "=f"(d[0]), "=f"(d[1]), "=f"(d[2]), "=f"(d[3])
        : "r"(a[0]), "r"(a[1]), "r"(a[2]), "r"(a[3]), "r"(b0), "r"(b1), "f"(z));
}

// ---------------- prep: weights -> fragment-linear fp16 ----------------
__device__ __forceinline__ float wfetch(const float* W, int Nf, int n, int kk, bool c0) {
    if (n >= Nf) return 0.f;
    int src;
    if (c0) {                       // concat layout: [d 0..31, zero@32, geo@33..47]
        if (kk < 32) src = kk;
        else if (kk == 32) return 0.f;
        else src = kk - 1;
        if (src >= 47) return 0.f;
    } else {
        src = kk;
    }
    return W[src * Nf + n];
}

__global__ void prep_kernel(const float* __restrict__ Ws0, const float* __restrict__ Ws1,
                            const float* __restrict__ Ws2, const float* __restrict__ Wc0,
                            const float* __restrict__ Wc1, const float* __restrict__ Wc2,
                            const float* __restrict__ Wc3) {
    int i = blockIdx.x * blockDim.x + threadIdx.x;
    if (i >= WU4) return;
    const float* W; int Kf, Nf, KH, q; bool c0 = false;
    if      (i < 256)  { W = Ws0; Kf = 32; Nf = 64; KH = 1; q = i;        }
    else if (i < 768)  { W = Ws1; Kf = 64; Nf = 64; KH = 2; q = i - 256;  }
    else if (i < 896)  { W = Ws2; Kf = 64; Nf = 16; KH = 2; q = i - 768;  }
    else if (i < 1408) { W = Wc0; Kf = 48; Nf = 64; KH = 2; q = i - 896; c0 = true; }
    else if (i < 1920) { W = Wc1; Kf = 64; Nf = 64; KH = 2; q = i - 1408; }
    else if (i < 2432) { W = Wc2; Kf = 64; Nf = 64; KH = 2; q = i - 1920; }
    else               { W = Wc3; Kf = 64; Nf = 3;  KH = 2; q = i - 2432; }

    int lane = q & 31, t2 = q >> 5;
    int kh = t2 % KH, nt = t2 / KH;
    int g = lane >> 2, cp = lane & 3;
    int n = nt * 8 + g;

    auto pw = [&](int kk) -> float {
        return (kk < Kf) ? wfetch(W, Nf, n, kk, c0) : 0.f;
    };
    int k0 = 16 * (2 * kh) + 2 * cp;
    int k1 = 16 * (2 * kh + 1) + 2 * cp;
    uint4 v;
    v.x = h2pack(pw(k0),     pw(k0 + 1));
    v.y = h2pack(pw(k0 + 8), pw(k0 + 9));
    v.z = h2pack(pw(k1),     pw(k1 + 1));
    v.w = h2pack(pw(k1 + 8), pw(k1 + 9));
    wbuf[i] = v;
}

// ---------------- main kernel (M=32/warp, persistent, zero-C first MMA) ----------------

template <int KT, int NT>
__device__ __forceinline__ void layer_mma(const uint32_t (*aR)[4][4], const uint4* __restrict__ swL,
                                          int lane, float (*acc)[4]) {
    constexpr int KH = (KT + 1) / 2;
    constexpr int NG = (NT < 4) ? NT : 4;

#pragma unroll
    for (int kh = 0; kh < KH; kh++) {
#pragma unroll
        for (int h = 0; h < NT / NG; h++) {
            uint4 wv[NG];
#pragma unroll
            for (int j = 0; j < NG; j++)
                wv[j] = swL[((h * NG + j) * KH + kh) * 32 + lane];
#pragma unroll
            for (int j = 0; j < NG; j++)
#pragma unroll
                for (int mt = 0; mt < 2; mt++) {
                    if (kh == 0)
                        mma16z(acc[mt * NT + h * NG + j], aR[mt][0], wv[j].x, wv[j].y);
                    else
                        mma16(acc[mt * NT + h * NG + j], aR[mt][2 * kh], wv[j].x, wv[j].y);
                }
            if (2 * kh + 1 < KT) {
#pragma unroll
                for (int j = 0; j < NG; j++)
#pragma unroll
                    for (int mt = 0; mt < 2; mt++)
                        mma16(acc[mt * NT + h * NG + j], aR[mt][2 * kh + 1], wv[j].z, wv[j].w);
            }
        }
    }
}

__device__ __forceinline__ void cvt_relu8(const float (*acc)[4], uint32_t (*aR)[4][4]) {
#pragma unroll
    for (int mt = 0; mt < 2; mt++)
#pragma unroll
        for (int nt = 0; nt < 8; nt++) {
            int kt = nt >> 1, hi = (nt & 1) * 2;
            const float* dd = acc[mt * 8 + nt];
            aR[mt][kt][hi + 0] = h2relu(dd[0], dd[1]);
            aR[mt][kt][hi + 1] = h2relu(dd[2], dd[3]);
        }
}

// Load one warp's 32 rows of a [N,32] tensor into aR k-tiles 0,1 (fp16).
__device__ __forceinline__ void load_in(uint32_t (*aR)[4][4], const float* __restrict__ gsrc,
                                        int p0, int g, int cp) {
#pragma unroll
    for (int mt = 0; mt < 2; mt++)
#pragma unroll
        for (int kt = 0; kt < 2; kt++) {
            const float* ra = gsrc + (size_t)(p0 + mt * 16 + g) * 32 + 2 * cp + 16 * kt;
            const float* rb = ra + 8 * 32;
            float2 v0 = *(const float2*)(ra);
            float2 v1 = *(const float2*)(rb);
            float2 v2 = *(const float2*)(ra + 8);
            float2 v3 = *(const float2*)(rb + 8);
            aR[mt][kt][0] = h2pack(v0.x, v0.y);
            aR[mt][kt][1] = h2pack(v1.x, v1.y);
            aR[mt][kt][2] = h2pack(v2.x, v2.y);
            aR[mt][kt][3] = h2pack(v3.x, v3.y);
        }
}

__global__ __launch_bounds__(TPB, 2)
void RadianceFieldGrid_kernel(const float* __restrict__ x,
                              const float* __restrict__ din,
                              float* __restrict__ out, int N, int numTiles) {
    __shared__ uint4 sW[WU4];   // 39.9 KB

    const int t    = threadIdx.x;
    const int lane = t & 31;
    const int w    = t >> 5;
    const int g    = lane >> 2;
    const int cp   = lane & 3;

    // one-time weight copy; persistent CTA amortizes it over ~14 tiles
    for (int i = t; i < WU4; i += TPB) sW[i] = wbuf[i];
    __syncthreads();

    float* __restrict__ sigmaOut = out + (size_t)3 * N;

    uint32_t aR[2][4][4];
    float acc[16][4];

    for (int tile = blockIdx.x; tile < numTiles; tile += gridDim.x) {
        const int p0 = tile * 256 + w * 32;   // this warp's first point

        // ---- sigma net ----
        load_in(aR, x, p0, g, cp);
        layer_mma<2, 8>(aR, sW + OFF_S0, lane, acc);
        cvt_relu8(acc, aR);
        layer_mma<4, 8>(aR, sW + OFF_S1, lane, acc);
        cvt_relu8(acc, aR);
        layer_mma<4, 2>(aR, sW + OFF_S2, lane, acc);   // acc[mt*2+nt]

        // sigma = relu(col 0) -> out[3N + p]
        if (cp == 0) {
#pragma unroll
            for (int mt = 0; mt < 2; mt++) {
                sigmaOut[p0 + mt * 16 + g]     = fmaxf(acc[mt * 2][0], 0.f);
                sigmaOut[p0 + mt * 16 + g + 8] = fmaxf(acc[mt * 2][2], 0.f);
            }
        }

        // color A: k-tile 2 = relu(L2 D-frags); then d straight into k-tiles 0,1
        // (loaded HERE, at minimum register liveness -- only 8 acc regs live)
#pragma unroll
        for (int mt = 0; mt < 2; mt++) {
            const float* d0 = acc[mt * 2 + 0];
            const float* d1 = acc[mt * 2 + 1];
            aR[mt][2][0] = h2relu(d0[0], d0[1]);
            aR[mt][2][1] = h2relu(d0[2], d0[3]);
            aR[mt][2][2] = h2relu(d1[0], d1[1]);
            aR[mt][2][3] = h2relu(d1[2], d1[3]);
        }
        load_in(aR, din, p0, g, cp);   // writes aR[mt][0..1] directly

        // ---- color net ----
        layer_mma<3, 8>(aR, sW + OFF_C0, lane, acc);
        cvt_relu8(acc, aR);
        layer_mma<4, 8>(aR, sW + OFF_C1, lane, acc);
        cvt_relu8(acc, aR);
        layer_mma<4, 8>(aR, sW + OFF_C2, lane, acc);
        cvt_relu8(acc, aR);
        layer_mma<4, 1>(aR, sW + OFF_C3, lane, acc);   // acc[mt]

        // sigmoid + store color (cols 0..2)
#pragma unroll
        for (int mt = 0; mt < 2; mt++)
#pragma unroll
            for (int qq = 0; qq < 4; qq++) {
                int c = 2 * cp + (qq & 1);
                if (c < 3) {
                    int row = mt * 16 + g + 8 * (qq >> 1);
                    float v = acc[mt][qq];
                    out[(size_t)(p0 + row) * 3 + c] = 1.f / (1.f + __expf(-v));
                }
            }
    }
}

extern "C" void kernel_launch(void* const* d_in, const int* in_sizes, int n_in,
                              void* d_out, int out_size) {
    const float* x   = (const float*)d_in[0];
    const float* din = (const float*)d_in[1];
    const float* Ws0 = (const float*)d_in[2];
    const float* Ws1 = (const float*)d_in[3];
    const float* Ws2 = (const float*)d_in[4];
    const float* Wc0 = (const float*)d_in[5];
    const float* Wc1 = (const float*)d_in[6];
    const float* Wc2 = (const float*)d_in[7];
    const float* Wc3 = (const float*)d_in[8];
    float* out = (float*)d_out;

    int N = in_sizes[0] / 32;   // x is [N, 32]
    int numTiles = N / 256;     // 256 points per CTA-tile

    prep_kernel<<<(WU4 + 255) / 256, 256>>>(Ws0, Ws1, Ws2, Wc0, Wc1, Wc2, Wc3);
    RadianceFieldGrid_kernel<<<148 * 2, TPB>>>(x, din, out, N, numTiles);
}

// round 15
// speedup vs baseline: 1.0177x; 1.0177x over previous
#include <cuda_runtime.h>
#include <cuda_fp16.h>
#include <cstdint>

#define TPB 256

// ---- fragment-linear fp16 weight buffer ----
// Per (layer, nt, kh, lane): uint4 = (b0 kt=2kh, b1 kt=2kh, b0 kt=2kh+1, b1 kt=2kh+1)
// where b0 = f16x2 (W[k=16kt+2cp][n], W[k=16kt+2cp+1][n]), b1 = k+8, n = nt*8+g.
#define OFF_S0 0        // K=32 (KH=1), N=64: 256
#define OFF_S1 256      // K=64 (KH=2), N=64: 512
#define OFF_S2 768      // K=64, N=16: 128
#define OFF_C0 896      // K=48 permuted (KH=2), N=64: 512
#define OFF_C1 1408     // 512
#define OFF_C2 1920     // 512
#define OFF_C3 2432     // K=64, N=8: 64
#define WU4    2496

__device__ uint4 wbuf[WU4];

__device__ __forceinline__ uint32_t h2pack(float a, float b) {
    __half2 h = __floats2half2_rn(a, b);
    return *(uint32_t*)&h;
}
__device__ __forceinline__ uint32_t h2relu(float a, float b) {
    __half2 h = __floats2half2_rn(a, b);
    h = __hmax2(h, __half2(__float2half_rn(0.f), __float2half_rn(0.f)));
    return *(uint32_t*)&h;
}

__device__ __forceinline__ void mma16(float* d, const uint32_t* a, uint32_t b0, uint32_t b1) {
    asm volatile(
        "mma.sync.aligned.m16n8k16.row.col.f32.f16.f16.f32 "
        "{%0,%1,%2,%3}, {%4,%5,%6,%7}, {%8,%9}, {%0,%1,%2,%3};"
        : "+f"(d[0]), "+f"(d[1]), "+f"(d[2]), "+f"(d[3])
        : "r"(a[0]), "r"(a[1]), "r"(a[2]), "r"(a[3]), "r"(b0), "r"(b1));
}

// First-touch variant: D = A*B + 0 (no accumulator pre-init needed).
__device__ __forceinline__ void mma16z(float* d, const uint32_t* a, uint32_t b0, uint32_t b1) {
    float z = 0.f;
    asm volatile(
        "mma.sync.aligned.m16n8k16.row.col.f32.f16.f16.f32 "
        "{%0,%1,%2,%3}, {%4,%5,%6,%7}, {%8,%9}, {%10,%10,%10,%10};"
        : "=f"(d[0]), "=f"(d[1]), "=f"(d[2]), "=f"(d[3])
        : "r"(a[0]), "r"(a[1]), "r"(a[2]), "r"(a[3]), "r"(b0), "r"(b1), "f"(z));
}

// ---------------- prep: weights -> fragment-linear fp16 ----------------
__device__ __forceinline__ float wfetch(const float* W, int Nf, int n, int kk, bool c0) {
    if (n >= Nf) return 0.f;
    int src;
    if (c0) {                       // concat layout: [d 0..31, zero@32, geo@33..47]
        if (kk < 32) src = kk;
        else if (kk == 32) return 0.f;
        else src = kk - 1;
        if (src >= 47) return 0.f;
    } else {
        src = kk;
    }
    return W[src * Nf + n];
}

__global__ void prep_kernel(const float* __restrict__ Ws0, const float* __restrict__ Ws1,
                            const float* __restrict__ Ws2, const float* __restrict__ Wc0,
                            const float* __restrict__ Wc1, const float* __restrict__ Wc2,
                            const float* __restrict__ Wc3) {
    int i = blockIdx.x * blockDim.x + threadIdx.x;
    if (i >= WU4) return;
    const float* W; int Kf, Nf, KH, q; bool c0 = false;
    if      (i < 256)  { W = Ws0; Kf = 32; Nf = 64; KH = 1; q = i;        }
    else if (i < 768)  { W = Ws1; Kf = 64; Nf = 64; KH = 2; q = i - 256;  }
    else if (i < 896)  { W = Ws2; Kf = 64; Nf = 16; KH = 2; q = i - 768;  }
    else if (i < 1408) { W = Wc0; Kf = 48; Nf = 64; KH = 2; q = i - 896; c0 = true; }
    else if (i < 1920) { W = Wc1; Kf = 64; Nf = 64; KH = 2; q = i - 1408; }
    else if (i < 2432) { W = Wc2; Kf = 64; Nf = 64; KH = 2; q = i - 1920; }
    else               { W = Wc3; Kf = 64; Nf = 3;  KH = 2; q = i - 2432; }

    int lane = q & 31, t2 = q >> 5;
    int kh = t2 % KH, nt = t2 / KH;
    int g = lane >> 2, cp = lane & 3;
    int n = nt * 8 + g;

    auto pw = [&](int kk) -> float {
        return (kk < Kf) ? wfetch(W, Nf, n, kk, c0) : 0.f;
    };
    int k0 = 16 * (2 * kh) + 2 * cp;
    int k1 = 16 * (2 * kh + 1) + 2 * cp;
    uint4 v;
    v.x = h2pack(pw(k0),     pw(k0 + 1));
    v.y = h2pack(pw(k0 + 8), pw(k0 + 9));
    v.z = h2pack(pw(k1),     pw(k1 + 1));
    v.w = h2pack(pw(k1 + 8), pw(k1 + 9));
    wbuf[i] = v;
}

// ---------------- main kernel (M=32/warp, persistent, fused boundary cvt) ----------------

// cvt+relu for one 4-wide n-tile group h (nts h*4..h*4+3) -> aR k-tiles 2h, 2h+1.
__device__ __forceinline__ void cvt_group(const float (*acc)[4], uint32_t (*aR)[4][4], int h) {
#pragma unroll
    for (int mt = 0; mt < 2; mt++)
#pragma unroll
        for (int j = 0; j < 4; j++) {
            int nt = h * 4 + j;
            int kt = nt >> 1, hi = (nt & 1) * 2;
            const float* dd = acc[mt * 8 + nt];
            aR[mt][kt][hi + 0] = h2relu(dd[0], dd[1]);
            aR[mt][kt][hi + 1] = h2relu(dd[2], dd[3]);
        }
}

// FUSE: interleave the output cvt into the final kh sweep. Valid only when the
// final kh does NOT read aR[0..1] (i.e. KT >= 3). Group h0's cvts write
// aR[0..1] while h1's MMAs (reading aR[2](,3)) are still pending -> no hazard,
// and the next layer's kh0 can issue without waiting for this layer's drain.
template <int KT, int NT, bool FUSE>
__device__ __forceinline__ void layer_mma(uint32_t (*aR)[4][4], const uint4* __restrict__ swL,
                                          int lane, float (*acc)[4]) {
    constexpr int KH = (KT + 1) / 2;
    constexpr int NG = (NT < 4) ? NT : 4;
    static_assert(!FUSE || KT >= 3, "fused cvt requires last kh to not read aR[0..1]");
    static_assert(!FUSE || NT == 8, "fused cvt assumes 8 n-tiles");

#pragma unroll
    for (int kh = 0; kh < KH; kh++) {
        const bool last = (kh == KH - 1);
        uint4 wvn[NG];   // pre-loaded wv for the last-kh h1 group (FUSE path)
        if (FUSE && last) {
#pragma unroll
            for (int j = 0; j < NG; j++)
                wvn[j] = swL[((NG + j) * KH + kh) * 32 + lane];
        }
#pragma unroll
        for (int h = 0; h < NT / NG; h++) {
            uint4 wv[NG];
            if (FUSE && last && h == 1) {
#pragma unroll
                for (int j = 0; j < NG; j++) wv[j] = wvn[j];
            } else {
#pragma unroll
                for (int j = 0; j < NG; j++)
                    wv[j] = swL[((h * NG + j) * KH + kh) * 32 + lane];
            }
#pragma unroll
            for (int j = 0; j < NG; j++)
#pragma unroll
                for (int mt = 0; mt < 2; mt++) {
                    if (kh == 0)
                        mma16z(acc[mt * NT + h * NG + j], aR[mt][0], wv[j].x, wv[j].y);
                    else
                        mma16(acc[mt * NT + h * NG + j], aR[mt][2 * kh], wv[j].x, wv[j].y);
                }
            if (2 * kh + 1 < KT) {
#pragma unroll
                for (int j = 0; j < NG; j++)
#pragma unroll
                    for (int mt = 0; mt < 2; mt++)
                        mma16(acc[mt * NT + h * NG + j], aR[mt][2 * kh + 1], wv[j].z, wv[j].w);
            }
            // fused boundary: cvt this group's accs right after its MMAs issue
            if (FUSE && last)
                cvt_group(acc, aR, h);
        }
    }
}

__device__ __forceinline__ void cvt_relu8(const float (*acc)[4], uint32_t (*aR)[4][4]) {
    cvt_group(acc, aR, 0);
    cvt_group(acc, aR, 1);
}

// Load one warp's 32 rows of a [N,32] tensor into aR k-tiles 0,1 (fp16).
__device__ __forceinline__ void load_in(uint32_t (*aR)[4][4], const float* __restrict__ gsrc,
                                        int p0, int g, int cp) {
#pragma unroll
    for (int mt = 0; mt < 2; mt++)
#pragma unroll
        for (int kt = 0; kt < 2; kt++) {
            const float* ra = gsrc + (size_t)(p0 + mt * 16 + g) * 32 + 2 * cp + 16 * kt;
            const float* rb = ra + 8 * 32;
            float2 v0 = *(const float2*)(ra);
            float2 v1 = *(const float2*)(rb);
            float2 v2 = *(const float2*)(ra + 8);
            float2 v3 = *(const float2*)(rb + 8);
            aR[mt][kt][0] = h2pack(v0.x, v0.y);
            aR[mt][kt][1] = h2pack(v1.x, v1.y);
            aR[mt][kt][2] = h2pack(v2.x, v2.y);
            aR[mt][kt][3] = h2pack(v3.x, v3.y);
        }
}

__global__ __launch_bounds__(TPB, 2)
void RadianceFieldGrid_kernel(const float* __restrict__ x,
                              const float* __restrict__ din,
                              float* __restrict__ out, int N, int numTiles) {
    __shared__ uint4 sW[WU4];   // 39.9 KB

    const int t    = threadIdx.x;
    const int lane = t & 31;
    const int w    = t >> 5;
    const int g    = lane >> 2;
    const int cp   = lane & 3;

    // one-time weight copy; persistent CTA amortizes it over ~14 tiles
    for (int i = t; i < WU4; i += TPB) sW[i] = wbuf[i];
    __syncthreads();

    float* __restrict__ sigmaOut = out + (size_t)3 * N;

    uint32_t aR[2][4][4];
    float acc[16][4];

    for (int tile = blockIdx.x; tile < numTiles; tile += gridDim.x) {
        const int p0 = tile * 256 + w * 32;   // this warp's first point

        // ---- sigma net ----
        load_in(aR, x, p0, g, cp);
        layer_mma<2, 8, false>(aR, sW + OFF_S0, lane, acc);
        cvt_relu8(acc, aR);                                   // S0 can't fuse (reads aR[0,1])
        layer_mma<4, 8, true>(aR, sW + OFF_S1, lane, acc);    // fused cvt
        layer_mma<4, 2, false>(aR, sW + OFF_S2, lane, acc);   // acc[mt*2+nt]

        // sigma = relu(col 0) -> out[3N + p]
        if (cp == 0) {
#pragma unroll
            for (int mt = 0; mt < 2; mt++) {
                sigmaOut[p0 + mt * 16 + g]     = fmaxf(acc[mt * 2][0], 0.f);
                sigmaOut[p0 + mt * 16 + g + 8] = fmaxf(acc[mt * 2][2], 0.f);
            }
        }

        // color A: k-tile 2 = relu(L2 D-frags); then d straight into k-tiles 0,1
#pragma unroll
        for (int mt = 0; mt < 2; mt++) {
            const float* d0 = acc[mt * 2 + 0];
            const float* d1 = acc[mt * 2 + 1];
            aR[mt][2][0] = h2relu(d0[0], d0[1]);
            aR[mt][2][1] = h2relu(d0[2], d0[3]);
            aR[mt][2][2] = h2relu(d1[0], d1[1]);
            aR[mt][2][3] = h2relu(d1[2], d1[3]);
        }
        load_in(aR, din, p0, g, cp);   // writes aR[mt][0..1] directly

        // ---- color net ----
        layer_mma<3, 8, true>(aR, sW + OFF_C0, lane, acc);    // fused
        layer_mma<4, 8, true>(aR, sW + OFF_C1, lane, acc);    // fused
        layer_mma<4, 8, true>(aR, sW + OFF_C2, lane, acc);    // fused
        layer_mma<4, 1, false>(aR, sW + OFF_C3, lane, acc);   // acc[mt]

        // sigmoid + store color (cols 0..2)
#pragma unroll
        for (int mt = 0; mt < 2; mt++)
#pragma unroll
            for (int qq = 0; qq < 4; qq++) {
                int c = 2 * cp + (qq & 1);
                if (c < 3) {
                    int row = mt * 16 + g + 8 * (qq >> 1);
                    float v = acc[mt][qq];
                    out[(size_t)(p0 + row) * 3 + c] = 1.f / (1.f + __expf(-v));
                }
            }
    }
}

extern "C" void kernel_launch(void* const* d_in, const int* in_sizes, int n_in,
                              void* d_out, int out_size) {
    const float* x   = (const float*)d_in[0];
    const float* din = (const float*)d_in[1];
    const float* Ws0 = (const float*)d_in[2];
    const float* Ws1 = (const float*)d_in[3];
    const float* Ws2 = (const float*)d_in[4];
    const float* Wc0 = (const float*)d_in[5];
    const float* Wc1 = (const float*)d_in[6];
    const float* Wc2 = (const float*)d_in[7];
    const float* Wc3 = (const float*)d_in[8];
    float* out = (float*)d_out;

    int N = in_sizes[0] / 32;   // x is [N, 32]
    int numTiles = N / 256;     // 256 points per CTA-tile

    prep_kernel<<<(WU4 + 255) / 256, 256>>>(Ws0, Ws1, Ws2, Wc0, Wc1, Wc2, Wc3);
    RadianceFieldGrid_kernel<<<148 * 2, TPB>>>(x, din, out, N, numTiles);
}

// round 17
// speedup vs baseline: 1.0358x; 1.0177x over previous
#include <cuda_runtime.h>
#include <cuda_fp16.h>
#include <cstdint>

#define TPB 256

// ---- fragment-linear fp16 weight buffer ----
// Per (layer, nt, kh, lane): uint4 = (b0 even-kt, b1 even-kt, b0 odd-kt, b1 odd-kt)
// where b0 = f16x2 (W[k=16kt+2cp][n], W[k+1][n]), b1 = k+8, n = nt*8+g.
// In smem this is SPLIT into sWE (xy) and sWO (zw), each uint2[WU4], same slot index.
#define OFF_S0 0        // K=32 (KH=1), N=64: 256
#define OFF_S1 256      // K=64 (KH=2), N=64: 512
#define OFF_S2 768      // K=64, N=16: 128
#define OFF_C0 896      // K=48 permuted (KH=2), N=64: 512
#define OFF_C1 1408     // 512
#define OFF_C2 1920     // 512
#define OFF_C3 2432     // K=64, N=8: 64
#define WU4    2496

__device__ uint4 wbuf[WU4];

__device__ __forceinline__ uint32_t h2pack(float a, float b) {
    __half2 h = __floats2half2_rn(a, b);
    return *(uint32_t*)&h;
}
__device__ __forceinline__ uint32_t h2relu(float a, float b) {
    __half2 h = __floats2half2_rn(a, b);
    h = __hmax2(h, __half2(__float2half_rn(0.f), __float2half_rn(0.f)));
    return *(uint32_t*)&h;
}

__device__ __forceinline__ void mma16(float* d, const uint32_t* a, uint32_t b0, uint32_t b1) {
    asm volatile(
        "mma.sync.aligned.m16n8k16.row.col.f32.f16.f16.f32 "
        "{%0,%1,%2,%3}, {%4,%5,%6,%7}, {%8,%9}, {%0,%1,%2,%3};"
        : "+f"(d[0]), "+f"(d[1]), "+f"(d[2]), "+f"(d[3])
        : "r"(a[0]), "r"(a[1]), "r"(a[2]), "r"(a[3]), "r"(b0), "r"(b1));
}

// First-touch variant: D = A*B + 0 (no accumulator pre-init needed).
__device__ __forceinline__ void mma16z(float* d, const uint32_t* a, uint32_t b0, uint32_t b1) {
    float z = 0.f;
    asm volatile(
        "mma.sync.aligned.m16n8k16.row.col.f32.f16.f16.f32 "
        "{%0,%1,%2,%3}, {%4,%5,%6,%7}, {%8,%9}, {%10,%10,%10,%10};"
        : "=f"(d[0]), "=f"(d[1]), "=f"(d[2]), "=f"(d[3])
        : "r"(a[0]), "r"(a[1]), "r"(a[2]), "r"(a[3]), "r"(b0), "r"(b1), "f"(z));
}

// ---------------- prep: weights -> fragment-linear fp16 ----------------
__device__ __forceinline__ float wfetch(const float* W, int Nf, int n, int kk, bool c0) {
    if (n >= Nf) return 0.f;
    int src;
    if (c0) {                       // concat layout: [d 0..31, zero@32, geo@33..47]
        if (kk < 32) src = kk;
        else if (kk == 32) return 0.f;
        else src = kk - 1;
        if (src >= 47) return 0.f;
    } else {
        src = kk;
    }
    return W[src * Nf + n];
}

__global__ void prep_kernel(const float* __restrict__ Ws0, const float* __restrict__ Ws1,
                            const float* __restrict__ Ws2, const float* __restrict__ Wc0,
                            const float* __restrict__ Wc1, const float* __restrict__ Wc2,
                            const float* __restrict__ Wc3) {
    int i = blockIdx.x * blockDim.x + threadIdx.x;
    if (i >= WU4) return;
    const float* W; int Kf, Nf, KH, q; bool c0 = false;
    if      (i < 256)  { W = Ws0; Kf = 32; Nf = 64; KH = 1; q = i;        }
    else if (i < 768)  { W = Ws1; Kf = 64; Nf = 64; KH = 2; q = i - 256;  }
    else if (i < 896)  { W = Ws2; Kf = 64; Nf = 16; KH = 2; q = i - 768;  }
    else if (i < 1408) { W = Wc0; Kf = 48; Nf = 64; KH = 2; q = i - 896; c0 = true; }
    else if (i < 1920) { W = Wc1; Kf = 64; Nf = 64; KH = 2; q = i - 1408; }
    else if (i < 2432) { W = Wc2; Kf = 64; Nf = 64; KH = 2; q = i - 1920; }
    else               { W = Wc3; Kf = 64; Nf = 3;  KH = 2; q = i - 2432; }

    int lane = q & 31, t2 = q >> 5;
    int kh = t2 % KH, nt = t2 / KH;
    int g = lane >> 2, cp = lane & 3;
    int n = nt * 8 + g;

    auto pw = [&](int kk) -> float {
        return (kk < Kf) ? wfetch(W, Nf, n, kk, c0) : 0.f;
    };
    int k0 = 16 * (2 * kh) + 2 * cp;
    int k1 = 16 * (2 * kh + 1) + 2 * cp;
    uint4 v;
    v.x = h2pack(pw(k0),     pw(k0 + 1));
    v.y = h2pack(pw(k0 + 8), pw(k0 + 9));
    v.z = h2pack(pw(k1),     pw(k1 + 1));
    v.w = h2pack(pw(k1 + 8), pw(k1 + 9));
    wbuf[i] = v;
}

// ---------------- main kernel (M=32/warp, persistent, E/O phase-split B) ----------------

// cvt+relu for one 4-wide n-tile group h (nts h*4..h*4+3) -> aR k-tiles 2h, 2h+1.
__device__ __forceinline__ void cvt_group(const float (*acc)[4], uint32_t (*aR)[4][4], int h) {
#pragma unroll
    for (int mt = 0; mt < 2; mt++)
#pragma unroll
        for (int j = 0; j < 4; j++) {
            int nt = h * 4 + j;
            int kt = nt >> 1, hi = (nt & 1) * 2;
            const float* dd = acc[mt * 8 + nt];
            aR[mt][kt][hi + 0] = h2relu(dd[0], dd[1]);
            aR[mt][kt][hi + 1] = h2relu(dd[2], dd[3]);
        }
}

// Phase-split layer: per kh, sweep ALL n-tiles with even-k B halves (16 MMAs),
// then all with odd-k halves. Same-accumulator RAW spacing = 16 MMAs (>= HMMA
// latency) at no extra register cost: e[] and o[] reuse the same 16 registers.
// MMA order per accumulator is unchanged (kh asc, even before odd) -> numerics
// bit-identical to previous rounds.
template <int KT, int NT, bool FUSE>
__device__ __forceinline__ void layer_mma(uint32_t (*aR)[4][4],
                                          const uint2* __restrict__ swE,
                                          const uint2* __restrict__ swO,
                                          int lane, float (*acc)[4]) {
    constexpr int KH = (KT + 1) / 2;
    static_assert(!FUSE || KT >= 3, "fused cvt requires last kh to not read aR[0..1]");
    static_assert(!FUSE || NT == 8, "fused cvt assumes 8 n-tiles");

#pragma unroll
    for (int kh = 0; kh < KH; kh++) {
        const bool last   = (kh == KH - 1);
        const bool hasOdd = (2 * kh + 1 < KT);
        uint2 e[NT];
#pragma unroll
        for (int j = 0; j < NT; j++)
            e[j] = swE[(j * KH + kh) * 32 + lane];
#pragma unroll
        for (int j = 0; j < NT; j++)
#pragma unroll
            for (int mt = 0; mt < 2; mt++) {
                if (kh == 0)
                    mma16z(acc[mt * NT + j], aR[mt][0], e[j].x, e[j].y);
                else
                    mma16(acc[mt * NT + j], aR[mt][2 * kh], e[j].x, e[j].y);
            }
        if (hasOdd) {
            uint2 o[NT];
#pragma unroll
            for (int j = 0; j < NT; j++)
                o[j] = swO[(j * KH + kh) * 32 + lane];
#pragma unroll
            for (int j = 0; j < NT; j++) {
#pragma unroll
                for (int mt = 0; mt < 2; mt++)
                    mma16(acc[mt * NT + j], aR[mt][2 * kh + 1], o[j].x, o[j].y);
                // fused boundary cvt: nts 0..3 done once their odd MMAs issue;
                // writes aR[0,1] while remaining odd MMAs read aR[2kh+1>=3].
                if (FUSE && last && j == 3)
                    cvt_group(acc, aR, 0);
            }
            if (FUSE && last)
                cvt_group(acc, aR, 1);
        } else if (FUSE && last) {
            // KT==3: last kh is even-only (reads aR[2]); cvt after the sweep.
            cvt_group(acc, aR, 0);
            cvt_group(acc, aR, 1);
        }
    }
}

__device__ __forceinline__ void cvt_relu8(const float (*acc)[4], uint32_t (*aR)[4][4]) {
    cvt_group(acc, aR, 0);
    cvt_group(acc, aR, 1);
}

// Load one warp's 32 rows of a [N,32] tensor into aR k-tiles 0,1 (fp16).
__device__ __forceinline__ void load_in(uint32_t (*aR)[4][4], const float* __restrict__ gsrc,
                                        int p0, int g, int cp) {
#pragma unroll
    for (int mt = 0; mt < 2; mt++)
#pragma unroll
        for (int kt = 0; kt < 2; kt++) {
            const float* ra = gsrc + (size_t)(p0 + mt * 16 + g) * 32 + 2 * cp + 16 * kt;
            const float* rb = ra + 8 * 32;
            float2 v0 = *(const float2*)(ra);
            float2 v1 = *(const float2*)(rb);
            float2 v2 = *(const float2*)(ra + 8);
            float2 v3 = *(const float2*)(rb + 8);
            aR[mt][kt][0] = h2pack(v0.x, v0.y);
            aR[mt][kt][1] = h2pack(v1.x, v1.y);
            aR[mt][kt][2] = h2pack(v2.x, v2.y);
            aR[mt][kt][3] = h2pack(v3.x, v3.y);
        }
}

__global__ __launch_bounds__(TPB, 2)
void RadianceFieldGrid_kernel(const float* __restrict__ x,
                              const float* __restrict__ din,
                              float* __restrict__ out, int N, int numTiles) {
    __shared__ uint2 sWE[WU4];   // even-k B halves, 20 KB
    __shared__ uint2 sWO[WU4];   // odd-k  B halves, 20 KB

    const int t    = threadIdx.x;
    const int lane = t & 31;
    const int w    = t >> 5;
    const int g    = lane >> 2;
    const int cp   = lane & 3;

    // one-time weight copy + E/O split; persistent CTA amortizes over ~14 tiles
    for (int i = t; i < WU4; i += TPB) {
        uint4 v = wbuf[i];
        sWE[i] = make_uint2(v.x, v.y);
        sWO[i] = make_uint2(v.z, v.w);
    }
    __syncthreads();

    float* __restrict__ sigmaOut = out + (size_t)3 * N;

    uint32_t aR[2][4][4];
    float acc[16][4];

    for (int tile = blockIdx.x; tile < numTiles; tile += gridDim.x) {
        const int p0 = tile * 256 + w * 32;   // this warp's first point

        // ---- sigma net ----
        load_in(aR, x, p0, g, cp);
        layer_mma<2, 8, false>(aR, sWE + OFF_S0, sWO + OFF_S0, lane, acc);
        cvt_relu8(acc, aR);                                          // S0 can't fuse
        layer_mma<4, 8, true >(aR, sWE + OFF_S1, sWO + OFF_S1, lane, acc);
        layer_mma<4, 2, false>(aR, sWE + OFF_S2, sWO + OFF_S2, lane, acc);

        // sigma = relu(col 0) -> out[3N + p]
        if (cp == 0) {
#pragma unroll
            for (int mt = 0; mt < 2; mt++) {
                sigmaOut[p0 + mt * 16 + g]     = fmaxf(acc[mt * 2][0], 0.f);
                sigmaOut[p0 + mt * 16 + g + 8] = fmaxf(acc[mt * 2][2], 0.f);
            }
        }

        // color A: k-tile 2 = relu(L2 D-frags); then d straight into k-tiles 0,1
#pragma unroll
        for (int mt = 0; mt < 2; mt++) {
            const float* d0 = acc[mt * 2 + 0];
            const float* d1 = acc[mt * 2 + 1];
            aR[mt][2][0] = h2relu(d0[0], d0[1]);
            aR[mt][2][1] = h2relu(d0[2], d0[3]);
            aR[mt][2][2] = h2relu(d1[0], d1[1]);
            aR[mt][2][3] = h2relu(d1[2], d1[3]);
        }
        load_in(aR, din, p0, g, cp);   // writes aR[mt][0..1] directly

        // L2-prefetch next tile's inputs: one 128B row per lane, zero regs held
        {
            int nt2 = tile + gridDim.x;
            if (nt2 < numTiles) {
                const float* xp = x   + (size_t)(nt2 * 256 + w * 32 + lane) * 32;
                const float* dp = din + (size_t)(nt2 * 256 + w * 32 + lane) * 32;
                asm volatile("prefetch.global.L2 [%0];" :: "l"(xp));
                asm volatile("prefetch.global.L2 [%0];" :: "l"(dp));
            }
        }

        // ---- color net ----
        layer_mma<3, 8, true >(aR, sWE + OFF_C0, sWO + OFF_C0, lane, acc);
        layer_mma<4, 8, true >(aR, sWE + OFF_C1, sWO + OFF_C1, lane, acc);
        layer_mma<4, 8, true >(aR, sWE + OFF_C2, sWO + OFF_C2, lane, acc);
        layer_mma<4, 1, false>(aR, sWE + OFF_C3, sWO + OFF_C3, lane, acc);

        // sigmoid + store color (cols 0..2)
#pragma unroll
        for (int mt = 0; mt < 2; mt++)
#pragma unroll
            for (int qq = 0; qq < 4; qq++) {
                int c = 2 * cp + (qq & 1);
                if (c < 3) {
                    int row = mt * 16 + g + 8 * (qq >> 1);
                    float v = acc[mt][qq];
                    out[(size_t)(p0 + row) * 3 + c] = 1.f / (1.f + __expf(-v));
                }
            }
    }
}

extern "C" void kernel_launch(void* const* d_in, const int* in_sizes, int n_in,
                              void* d_out, int out_size) {
    const float* x   = (const float*)d_in[0];
    const float* din = (const float*)d_in[1];
    const float* Ws0 = (const float*)d_in[2];
    const float* Ws1 = (const float*)d_in[3];
    const float* Ws2 = (const float*)d_in[4];
    const float* Wc0 = (const float*)d_in[5];
    const float* Wc1 = (const float*)d_in[6];
    const float* Wc2 = (const float*)d_in[7];
    const float* Wc3 = (const float*)d_in[8];
    float* out = (float*)d_out;

    int N = in_sizes[0] / 32;   // x is [N, 32]
    int numTiles = N / 256;     // 256 points per CTA-tile

    prep_kernel<<<(WU4 + 255) / 256, 256>>>(Ws0, Ws1, Ws2, Wc0, Wc1, Wc2, Wc3);
    RadianceFieldGrid_kernel<<<148 * 2, TPB>>>(x, din, out, N, numTiles);
}